// round 3
// baseline (speedup 1.0000x reference)
#include <cuda_runtime.h>
#include <math.h>

#define F 256
#define HID 128
#define BATCH 2048
#define KTOP 15
#define NPAIR 65536
#define NSPLIT 8
#define RB 64                    // rows per block in big kernel
#define TC 64                    // column tile
#define STRIPE (NPAIR / NSPLIT)  // 8192
#define NTILES (STRIPE / TC)     // 128
#define HP 68                    // h_s row pad (float4-aligned, conflict-light)
#define ZP 65                    // z_s row pad
#define NCAND (NSPLIT * 2 * KTOP)  // 240 candidates per row

// output layout offsets
#define PI_OFF (BATCH * KTOP)        // 30720
#define OP_OFF (PI_OFF + KTOP)       // 30735
#define RM_OFF (OP_OFF + 4)          // 30739
#define ENT_OFF (RM_OFF + KTOP)      // 30754

// -------- device scratch (static, no runtime alloc) --------
__device__ float g_hT[HID * BATCH];              // rs hidden, transposed [k][row]
__device__ float g_tf[BATCH * F];                // feature transform output
__device__ float g_opw[BATCH * 4];               // softmax op weights
__device__ float g_candv[BATCH * NCAND];         // top-k candidate logits
__device__ int   g_candi[BATCH * NCAND];         // top-k candidate pair indices
__device__ float g_entp[32 * NSPLIT];            // per-CTA entropy partials
__device__ float g_topsel[BATCH * KTOP];         // sigmoid values of winners

// =====================================================================
// Kernel 1: the three small MLPs. 8 rows per CTA, 256 threads.
// =====================================================================
__device__ __forceinline__ void hidden_layer(
    const float xs[8][F], const float* __restrict__ w1,
    const float* __restrict__ b1, int hcol, int rg, float out4[4])
{
    float a0 = 0.f, a1 = 0.f, a2 = 0.f, a3 = 0.f;
    #pragma unroll 4
    for (int f = 0; f < F; f++) {
        float wv = w1[f * HID + hcol];
        a0 = fmaf(xs[rg * 4 + 0][f], wv, a0);
        a1 = fmaf(xs[rg * 4 + 1][f], wv, a1);
        a2 = fmaf(xs[rg * 4 + 2][f], wv, a2);
        a3 = fmaf(xs[rg * 4 + 3][f], wv, a3);
    }
    float bb = b1[hcol];
    out4[0] = fmaxf(a0 + bb, 0.f);
    out4[1] = fmaxf(a1 + bb, 0.f);
    out4[2] = fmaxf(a2 + bb, 0.f);
    out4[3] = fmaxf(a3 + bb, 0.f);
}

__global__ __launch_bounds__(256) void prep_kernel(
    const float* __restrict__ x,
    const float* __restrict__ rs_w1, const float* __restrict__ rs_b1,
    const float* __restrict__ os_w1, const float* __restrict__ os_b1,
    const float* __restrict__ os_w2, const float* __restrict__ os_b2,
    const float* __restrict__ ft_w1, const float* __restrict__ ft_b1,
    const float* __restrict__ ft_w2, const float* __restrict__ ft_b2)
{
    __shared__ float xs[8][F];
    __shared__ float hb[8][HID];
    __shared__ float lg[8][4];
    const int tid = threadIdx.x;
    const int row0 = blockIdx.x * 8;

    for (int idx = tid; idx < 8 * F; idx += 256) {
        int r = idx >> 8, c = idx & (F - 1);
        xs[r][c] = x[(row0 + r) * F + c];
    }
    __syncthreads();

    const int hcol = tid & (HID - 1);
    const int rg = tid >> 7;   // 0..1

    // ---- rs hidden -> g_hT (transposed layout for the big kernel) ----
    {
        float h4[4];
        hidden_layer(xs, rs_w1, rs_b1, hcol, rg, h4);
        #pragma unroll
        for (int j = 0; j < 4; j++)
            g_hT[hcol * BATCH + row0 + rg * 4 + j] = h4[j];
    }

    // ---- ft hidden -> hb ----
    {
        float h4[4];
        hidden_layer(xs, ft_w1, ft_b1, hcol, rg, h4);
        #pragma unroll
        for (int j = 0; j < 4; j++) hb[rg * 4 + j][hcol] = h4[j];
    }
    __syncthreads();

    // ---- tf = hb @ ft_w2 + ft_b2 ----
    {
        const int o = tid;   // 0..255
        float a[8];
        #pragma unroll
        for (int r = 0; r < 8; r++) a[r] = 0.f;
        #pragma unroll 4
        for (int k = 0; k < HID; k++) {
            float wv = ft_w2[k * F + o];
            #pragma unroll
            for (int r = 0; r < 8; r++) a[r] = fmaf(hb[r][k], wv, a[r]);
        }
        float bb = ft_b2[o];
        #pragma unroll
        for (int r = 0; r < 8; r++)
            g_tf[(row0 + r) * F + o] = a[r] + bb;
    }
    __syncthreads();

    // ---- os hidden -> hb ----
    {
        float h4[4];
        hidden_layer(xs, os_w1, os_b1, hcol, rg, h4);
        #pragma unroll
        for (int j = 0; j < 4; j++) hb[rg * 4 + j][hcol] = h4[j];
    }
    __syncthreads();

    // ---- op logits ----
    if (tid < 32) {
        int r = tid >> 2, j = tid & 3;
        float a = os_b2[j];
        #pragma unroll 4
        for (int k = 0; k < HID; k++) a = fmaf(hb[r][k], os_w2[k * 4 + j], a);
        lg[r][j] = a;
    }
    __syncthreads();
    // ---- softmax over 4 ops ----
    if (tid < 8) {
        float l0 = lg[tid][0], l1 = lg[tid][1], l2 = lg[tid][2], l3 = lg[tid][3];
        float m = fmaxf(fmaxf(l0, l1), fmaxf(l2, l3));
        float e0 = __expf(l0 - m), e1 = __expf(l1 - m);
        float e2 = __expf(l2 - m), e3 = __expf(l3 - m);
        float inv = __fdividef(1.f, e0 + e1 + e2 + e3);
        g_opw[(row0 + tid) * 4 + 0] = e0 * inv;
        g_opw[(row0 + tid) * 4 + 1] = e1 * inv;
        g_opw[(row0 + tid) * 4 + 2] = e2 * inv;
        g_opw[(row0 + tid) * 4 + 3] = e3 * inv;
    }
}

// =====================================================================
// Kernel 2: fused [64,128]x[128,8192] logit GEMM + entropy + top-k.
// grid (32 row-blocks, 8 stripes), 128 threads/CTA, 2 CTAs/SM.
// Per-thread GEMM micro-tile: 4 rows x 8 cols (32 accumulators).
// Epilogue: 2 threads per row, per-thread register top-15 list.
// =====================================================================
extern __shared__ float smem2[];

__global__ __launch_bounds__(128, 2) void big_kernel(
    const float* __restrict__ w2, const float* __restrict__ b2)
{
    float* h_s = smem2;                  // [HID][HP]
    float* w_s = h_s + HID * HP;         // [HID][TC]
    float* z_s = w_s + HID * TC;         // [RB][ZP]

    const int tid = threadIdx.x;
    const int bx = blockIdx.x;           // row block 0..31
    const int by = blockIdx.y;           // stripe 0..7
    const int row0 = bx * RB;

    // load h (already transposed in global): coalesced, conflict-free STS
    for (int idx = tid; idx < HID * RB; idx += 128) {
        int k = idx >> 6;
        int r = idx & 63;
        h_s[k * HP + r] = g_hT[k * BATCH + row0 + r];
    }

    // per-thread top-k state (register arrays, fully unrolled access)
    float tv[KTOP];
    int ti[KTOP];
    #pragma unroll
    for (int s = 0; s < KTOP; s++) { tv[s] = -1e30f; ti[s] = 0x7fffffff; }
    float mn = -1e30f;
    int mnpos = 0;
    float ent = 0.f;

    const int rowg = tid & 15;   // row group: rows 4*rowg..+3
    const int colg = tid >> 4;   // col group: cols 8*colg..+7
    const int erow = tid >> 1;   // epilogue row 0..63
    const int esub = tid & 1;

    for (int tile = 0; tile < NTILES; tile++) {
        const int colbase = by * STRIPE + tile * TC;

        // stage w2 tile [128 x 64] into smem (coalesced LDG.128)
        #pragma unroll
        for (int i = 0; i < 16; i++) {
            int idx4 = tid + i * 128;              // 0..2047 float4s
            int k = idx4 >> 4;
            int c4 = (idx4 & 15) << 2;
            float4 v = *(const float4*)(w2 + (size_t)k * NPAIR + colbase + c4);
            *(float4*)(w_s + k * TC + c4) = v;
        }
        __syncthreads();

        float acc[4][8];
        #pragma unroll
        for (int i = 0; i < 4; i++)
            #pragma unroll
            for (int j = 0; j < 8; j++) acc[i][j] = 0.f;

        #pragma unroll 8
        for (int k = 0; k < HID; k++) {
            float4 hv = *(const float4*)(h_s + k * HP + 4 * rowg);
            float4 wa = *(const float4*)(w_s + k * TC + 8 * colg);
            float4 wb = *(const float4*)(w_s + k * TC + 8 * colg + 4);
            float hr[4] = {hv.x, hv.y, hv.z, hv.w};
            float wc[8] = {wa.x, wa.y, wa.z, wa.w, wb.x, wb.y, wb.z, wb.w};
            #pragma unroll
            for (int i = 0; i < 4; i++)
                #pragma unroll
                for (int j = 0; j < 8; j++)
                    acc[i][j] = fmaf(hr[i], wc[j], acc[i][j]);
        }

        // bias + stage z tile to smem
        float4 ba = *(const float4*)(b2 + colbase + 8 * colg);
        float4 bb = *(const float4*)(b2 + colbase + 8 * colg + 4);
        float bc[8] = {ba.x, ba.y, ba.z, ba.w, bb.x, bb.y, bb.z, bb.w};
        #pragma unroll
        for (int i = 0; i < 4; i++) {
            int r = 4 * rowg + i;
            #pragma unroll
            for (int j = 0; j < 8; j++)
                z_s[r * ZP + 8 * colg + j] = acc[i][j] + bc[j];
        }
        __syncthreads();

        // epilogue: entropy + top-k on raw logits (sigmoid is monotone)
        for (int i = 0; i < 32; i++) {
            int cc = esub + 2 * i;
            float z = z_s[erow * ZP + cc];
            // -s*ln(s) = ln(1+e^-z)/(1+e^-z); clamp for overflow safety
            float t = __expf(fminf(-z, 80.f));
            float a = 1.f + t;
            ent += __fdividef(__logf(a), a);
            if (z > mn) {
                int gcol = colbase + cc;
                #pragma unroll
                for (int s = 0; s < KTOP; s++)
                    if (s == mnpos) { tv[s] = z; ti[s] = gcol; }
                mn = tv[0]; mnpos = 0;
                #pragma unroll
                for (int s = 1; s < KTOP; s++)
                    if (tv[s] < mn) { mn = tv[s]; mnpos = s; }
            }
        }
        // next tile's w_s STS is safe without a third barrier: all compute
        // reads of w_s finished before the sync above.
    }

    // write candidates
    {
        int rowglob = row0 + erow;
        int base = ((rowglob * NSPLIT + by) * 2 + esub) * KTOP;
        #pragma unroll
        for (int s = 0; s < KTOP; s++) {
            g_candv[base + s] = tv[s];
            g_candi[base + s] = ti[s];
        }
    }

    // deterministic entropy reduction (tree in smem, no atomics)
    __syncthreads();
    z_s[tid] = ent;
    __syncthreads();
    #pragma unroll
    for (int off = 64; off > 0; off >>= 1) {
        if (tid < off) z_s[tid] += z_s[tid + off];
        __syncthreads();
    }
    if (tid == 0) g_entp[bx * NSPLIT + by] = z_s[0];
}

// =====================================================================
// Kernel 3: per-row merge of 240 candidates -> ordered top-15,
// gather tf, apply 4 ops weighted by op_w, write ratio_tensor.
// One warp per row. Lexicographic (value desc, index asc) = jax.top_k.
// =====================================================================
__global__ __launch_bounds__(128) void merge_kernel(float* __restrict__ out)
{
    const int warp = threadIdx.x >> 5;
    const int lane = threadIdx.x & 31;
    const int row = blockIdx.x * 4 + warp;

    float cv[8]; int ci[8];
    #pragma unroll
    for (int j = 0; j < 8; j++) {
        int s = lane + 32 * j;
        if (s < NCAND) {
            cv[j] = g_candv[row * NCAND + s];
            ci[j] = g_candi[row * NCAND + s];
        } else {
            cv[j] = -1e30f; ci[j] = 0x7fffffff;
        }
    }

    float ow0 = g_opw[row * 4 + 0], ow1 = g_opw[row * 4 + 1];
    float ow2 = g_opw[row * 4 + 2], ow3 = g_opw[row * 4 + 3];

    unsigned used = 0;
    for (int rank = 0; rank < KTOP; rank++) {
        float lv = -1e30f; int li = 0x7fffffff; int ls = -1;
        #pragma unroll
        for (int j = 0; j < 8; j++) {
            bool free = !((used >> j) & 1u);
            if (free && (cv[j] > lv || (cv[j] == lv && ci[j] < li))) {
                lv = cv[j]; li = ci[j]; ls = j;
            }
        }
        float gv = lv; int gi = li;
        #pragma unroll
        for (int off = 16; off > 0; off >>= 1) {
            float ov = __shfl_xor_sync(0xffffffffu, gv, off);
            int oi = __shfl_xor_sync(0xffffffffu, gi, off);
            if (ov > gv || (ov == gv && oi < gi)) { gv = ov; gi = oi; }
        }
        if (ls >= 0 && lv == gv && li == gi) used |= 1u << ls;

        if (lane == 0) {
            float sel = __fdividef(1.f, 1.f + __expf(-gv));
            int ii = gi >> 8, jj = gi & 255;
            float fi = g_tf[row * F + ii];
            float fj = g_tf[row * F + jj];
            float ratio = fi / (fabsf(fj) + 1e-8f);
            float lr = logf(fabsf(fi) + 1e-8f) - logf(fabsf(fj) + 1e-8f);
            float rt = ratio * ow0 + lr * ow1 + (fi - fj) * ow2 + (fi * fj) * ow3;
            out[row * KTOP + rank] = rt;
            g_topsel[row * KTOP + rank] = sel;
        }
    }
}

// =====================================================================
// Kernel 4: batch means (deterministic tree reductions), output tail.
// =====================================================================
__global__ __launch_bounds__(256) void final_kernel(float* __restrict__ out)
{
    __shared__ float red[256];
    const int tid = threadIdx.x;
    const float invB = 1.0f / (float)BATCH;

    // pair_importances
    for (int k = 0; k < KTOP; k++) {
        float p = 0.f;
        for (int r = tid; r < BATCH; r += 256) p += g_topsel[r * KTOP + k];
        red[tid] = p; __syncthreads();
        for (int off = 128; off > 0; off >>= 1) {
            if (tid < off) red[tid] += red[tid + off];
            __syncthreads();
        }
        if (tid == 0) out[PI_OFF + k] = red[0] * invB;
        __syncthreads();
    }
    // ratio_mags
    for (int k = 0; k < KTOP; k++) {
        float p = 0.f;
        for (int r = tid; r < BATCH; r += 256) p += fabsf(out[r * KTOP + k]);
        red[tid] = p; __syncthreads();
        for (int off = 128; off > 0; off >>= 1) {
            if (tid < off) red[tid] += red[tid + off];
            __syncthreads();
        }
        if (tid == 0) out[RM_OFF + k] = red[0] * invB;
        __syncthreads();
    }
    // op_prefs
    for (int j = 0; j < 4; j++) {
        float p = 0.f;
        for (int r = tid; r < BATCH; r += 256) p += g_opw[r * 4 + j];
        red[tid] = p; __syncthreads();
        for (int off = 128; off > 0; off >>= 1) {
            if (tid < off) red[tid] += red[tid + off];
            __syncthreads();
        }
        if (tid == 0) out[OP_OFF + j] = red[0] * invB;
        __syncthreads();
    }
    // entropy (256 CTA partials)
    {
        float p = g_entp[tid];
        red[tid] = p; __syncthreads();
        for (int off = 128; off > 0; off >>= 1) {
            if (tid < off) red[tid] += red[tid + off];
            __syncthreads();
        }
        if (tid == 0) out[ENT_OFF] = red[0] * invB;
    }
}

// =====================================================================
extern "C" void kernel_launch(void* const* d_in, const int* in_sizes, int n_in,
                              void* d_out, int out_size)
{
    const float* x     = (const float*)d_in[0];
    const float* rs_w1 = (const float*)d_in[1];
    const float* rs_b1 = (const float*)d_in[2];
    const float* rs_w2 = (const float*)d_in[3];
    const float* rs_b2 = (const float*)d_in[4];
    const float* os_w1 = (const float*)d_in[5];
    const float* os_b1 = (const float*)d_in[6];
    const float* os_w2 = (const float*)d_in[7];
    const float* os_b2 = (const float*)d_in[8];
    const float* ft_w1 = (const float*)d_in[9];
    const float* ft_b1 = (const float*)d_in[10];
    const float* ft_w2 = (const float*)d_in[11];
    const float* ft_b2 = (const float*)d_in[12];
    float* out = (float*)d_out;

    prep_kernel<<<BATCH / 8, 256>>>(x, rs_w1, rs_b1, os_w1, os_b1,
                                    os_w2, os_b2, ft_w1, ft_b1, ft_w2, ft_b2);

    const int smem_bytes = (HID * HP + HID * TC + RB * ZP) * (int)sizeof(float); // 84224
    cudaFuncSetAttribute(big_kernel, cudaFuncAttributeMaxDynamicSharedMemorySize,
                         smem_bytes);
    big_kernel<<<dim3(32, NSPLIT), 128, smem_bytes>>>(rs_w2, rs_b2);

    merge_kernel<<<BATCH / 4, 128>>>(out);
    final_kernel<<<1, 256>>>(out);
}

// round 4
// speedup vs baseline: 1.0203x; 1.0203x over previous
#include <cuda_runtime.h>
#include <math.h>

#define F 256
#define HID 128
#define BATCH 2048
#define KTOP 15
#define NPAIR 65536
#define NSPLIT 8
#define RB 128                   // rows per block in big kernel
#define TC 128                   // column tile
#define STRIPE (NPAIR / NSPLIT)  // 8192
#define NTILES (STRIPE / TC)     // 64
#define HP 132                   // h_s row pad
#define ZP 65                    // z_s row pad
#define NRB (BATCH / RB)         // 16 row blocks
#define NCAND (NSPLIT * 2 * KTOP)  // 240 candidates per row

// output layout offsets
#define PI_OFF (BATCH * KTOP)        // 30720
#define OP_OFF (PI_OFF + KTOP)       // 30735
#define RM_OFF (OP_OFF + 4)          // 30739
#define ENT_OFF (RM_OFF + KTOP)      // 30754

// -------- device scratch (static, no runtime alloc) --------
__device__ float g_hT[HID * BATCH];              // rs hidden, transposed [k][row]
__device__ float g_tf[BATCH * F];                // feature transform output
__device__ float g_opw[BATCH * 4];               // softmax op weights
__device__ float g_candv[BATCH * NCAND];         // top-k candidate logits
__device__ int   g_candi[BATCH * NCAND];         // top-k candidate pair indices
__device__ float g_entp[NRB * NSPLIT];           // per-CTA entropy partials (128)
__device__ float g_topsel[BATCH * KTOP];         // sigmoid values of winners

// -------- packed f32x2 helpers (sm_103a FFMA2 path) --------
__device__ __forceinline__ void ffma2(unsigned long long& d,
                                      unsigned long long a,
                                      unsigned long long b) {
    asm("fma.rn.f32x2 %0, %1, %2, %0;" : "+l"(d) : "l"(a), "l"(b));
}
__device__ __forceinline__ unsigned long long pack2(float lo, float hi) {
    unsigned long long r;
    asm("mov.b64 %0, {%1, %2};" : "=l"(r) : "f"(lo), "f"(hi));
    return r;
}
__device__ __forceinline__ float2 unpack2(unsigned long long v) {
    float2 r;
    asm("mov.b64 {%0, %1}, %2;" : "=f"(r.x), "=f"(r.y) : "l"(v));
    return r;
}

// =====================================================================
// Kernel 1: the three small MLPs. 8 rows per CTA, 256 threads.
// =====================================================================
__device__ __forceinline__ void hidden_layer(
    const float xs[8][F], const float* __restrict__ w1,
    const float* __restrict__ b1, int hcol, int rg, float out4[4])
{
    float a0 = 0.f, a1 = 0.f, a2 = 0.f, a3 = 0.f;
    #pragma unroll 4
    for (int f = 0; f < F; f++) {
        float wv = w1[f * HID + hcol];
        a0 = fmaf(xs[rg * 4 + 0][f], wv, a0);
        a1 = fmaf(xs[rg * 4 + 1][f], wv, a1);
        a2 = fmaf(xs[rg * 4 + 2][f], wv, a2);
        a3 = fmaf(xs[rg * 4 + 3][f], wv, a3);
    }
    float bb = b1[hcol];
    out4[0] = fmaxf(a0 + bb, 0.f);
    out4[1] = fmaxf(a1 + bb, 0.f);
    out4[2] = fmaxf(a2 + bb, 0.f);
    out4[3] = fmaxf(a3 + bb, 0.f);
}

__global__ __launch_bounds__(256) void prep_kernel(
    const float* __restrict__ x,
    const float* __restrict__ rs_w1, const float* __restrict__ rs_b1,
    const float* __restrict__ os_w1, const float* __restrict__ os_b1,
    const float* __restrict__ os_w2, const float* __restrict__ os_b2,
    const float* __restrict__ ft_w1, const float* __restrict__ ft_b1,
    const float* __restrict__ ft_w2, const float* __restrict__ ft_b2)
{
    __shared__ float xs[8][F];
    __shared__ float hb[8][HID];
    __shared__ float lg[8][4];
    const int tid = threadIdx.x;
    const int row0 = blockIdx.x * 8;

    for (int idx = tid; idx < 8 * F; idx += 256) {
        int r = idx >> 8, c = idx & (F - 1);
        xs[r][c] = x[(row0 + r) * F + c];
    }
    __syncthreads();

    const int hcol = tid & (HID - 1);
    const int rg = tid >> 7;   // 0..1

    // ---- rs hidden -> g_hT (transposed layout for the big kernel) ----
    {
        float h4[4];
        hidden_layer(xs, rs_w1, rs_b1, hcol, rg, h4);
        #pragma unroll
        for (int j = 0; j < 4; j++)
            g_hT[hcol * BATCH + row0 + rg * 4 + j] = h4[j];
    }

    // ---- ft hidden -> hb ----
    {
        float h4[4];
        hidden_layer(xs, ft_w1, ft_b1, hcol, rg, h4);
        #pragma unroll
        for (int j = 0; j < 4; j++) hb[rg * 4 + j][hcol] = h4[j];
    }
    __syncthreads();

    // ---- tf = hb @ ft_w2 + ft_b2 ----
    {
        const int o = tid;   // 0..255
        float a[8];
        #pragma unroll
        for (int r = 0; r < 8; r++) a[r] = 0.f;
        #pragma unroll 4
        for (int k = 0; k < HID; k++) {
            float wv = ft_w2[k * F + o];
            #pragma unroll
            for (int r = 0; r < 8; r++) a[r] = fmaf(hb[r][k], wv, a[r]);
        }
        float bb = ft_b2[o];
        #pragma unroll
        for (int r = 0; r < 8; r++)
            g_tf[(row0 + r) * F + o] = a[r] + bb;
    }
    __syncthreads();

    // ---- os hidden -> hb ----
    {
        float h4[4];
        hidden_layer(xs, os_w1, os_b1, hcol, rg, h4);
        #pragma unroll
        for (int j = 0; j < 4; j++) hb[rg * 4 + j][hcol] = h4[j];
    }
    __syncthreads();

    // ---- op logits ----
    if (tid < 32) {
        int r = tid >> 2, j = tid & 3;
        float a = os_b2[j];
        #pragma unroll 4
        for (int k = 0; k < HID; k++) a = fmaf(hb[r][k], os_w2[k * 4 + j], a);
        lg[r][j] = a;
    }
    __syncthreads();
    // ---- softmax over 4 ops ----
    if (tid < 8) {
        float l0 = lg[tid][0], l1 = lg[tid][1], l2 = lg[tid][2], l3 = lg[tid][3];
        float m = fmaxf(fmaxf(l0, l1), fmaxf(l2, l3));
        float e0 = __expf(l0 - m), e1 = __expf(l1 - m);
        float e2 = __expf(l2 - m), e3 = __expf(l3 - m);
        float inv = __fdividef(1.f, e0 + e1 + e2 + e3);
        g_opw[(row0 + tid) * 4 + 0] = e0 * inv;
        g_opw[(row0 + tid) * 4 + 1] = e1 * inv;
        g_opw[(row0 + tid) * 4 + 2] = e2 * inv;
        g_opw[(row0 + tid) * 4 + 3] = e3 * inv;
    }
}

// =====================================================================
// Kernel 2: fused [128,128]x[128,8192] logit GEMM + entropy + top-k.
// grid (16 row-blocks, 8 stripes) = 128 CTAs, 256 threads, 1 CTA/SM.
// Per-thread GEMM micro-tile: 8 rows x 8 cols via packed fma.rn.f32x2
// (32 FFMA2/thread/k -> 128 lane-MACs/cyc/SM, 2x the FFMA floor).
// Epilogue in two 64-col passes through padded smem staging.
// =====================================================================
extern __shared__ float smem2[];

__global__ __launch_bounds__(256, 1) void big_kernel(
    const float* __restrict__ w2, const float* __restrict__ b2)
{
    float* h_s = smem2;                  // [HID][HP]     67,584 B
    float* w_s = h_s + HID * HP;         // [HID][TC]     65,536 B
    float* z_s = w_s + HID * TC;         // [RB][ZP]      33,280 B

    const int tid = threadIdx.x;
    const int bx = blockIdx.x;           // row block 0..15
    const int by = blockIdx.y;           // stripe 0..7
    const int row0 = bx * RB;

    // load h (already transposed in global): coalesced, conflict-free STS
    for (int idx = tid; idx < HID * RB; idx += 256) {
        int k = idx >> 7;
        int r = idx & (RB - 1);
        h_s[k * HP + r] = g_hT[k * BATCH + row0 + r];
    }

    // per-thread top-k state (register arrays, fully unrolled access)
    float tv[KTOP];
    int ti[KTOP];
    #pragma unroll
    for (int s = 0; s < KTOP; s++) { tv[s] = -1e30f; ti[s] = 0x7fffffff; }
    float mn = -1e30f;
    int mnpos = 0;
    float ent = 0.f;

    const int rowg = tid >> 4;   // 0..15: rows 8*rowg..+7
    const int colg = tid & 15;   // 0..15: cols 8*colg..+7
    const int chalf = colg >> 3; // which 64-col half this thread's cols are in
    const int erow = tid >> 1;   // epilogue row 0..127
    const int esub = tid & 1;

    __syncthreads();

    for (int tile = 0; tile < NTILES; tile++) {
        const int colbase = by * STRIPE + tile * TC;

        // stage w2 tile [128 x 128] into smem (coalesced LDG.128)
        #pragma unroll
        for (int i = 0; i < 16; i++) {
            int idx4 = tid + i * 256;              // 0..4095 float4s
            int k = idx4 >> 5;
            int c4 = (idx4 & 31) << 2;
            float4 v = *(const float4*)(w2 + (size_t)k * NPAIR + colbase + c4);
            *(float4*)(w_s + k * TC + c4) = v;
        }
        __syncthreads();

        unsigned long long acc[8][4];
        #pragma unroll
        for (int i = 0; i < 8; i++)
            #pragma unroll
            for (int j = 0; j < 4; j++) acc[i][j] = 0ull;

        #pragma unroll 4
        for (int k = 0; k < HID; k++) {
            const float4 hv0 = *(const float4*)(h_s + k * HP + 8 * rowg);
            const float4 hv1 = *(const float4*)(h_s + k * HP + 8 * rowg + 4);
            const ulonglong2 wv0 = *(const ulonglong2*)(w_s + k * TC + 8 * colg);
            const ulonglong2 wv1 = *(const ulonglong2*)(w_s + k * TC + 8 * colg + 4);
            const unsigned long long wp[4] = {wv0.x, wv0.y, wv1.x, wv1.y};
            const float hr[8] = {hv0.x, hv0.y, hv0.z, hv0.w,
                                 hv1.x, hv1.y, hv1.z, hv1.w};
            #pragma unroll
            for (int i = 0; i < 8; i++) {
                unsigned long long hs = pack2(hr[i], hr[i]);
                #pragma unroll
                for (int j = 0; j < 4; j++) ffma2(acc[i][j], hs, wp[j]);
            }
        }

        // bias (per-thread 8 cols)
        float bc[8];
        {
            float4 ba = *(const float4*)(b2 + colbase + 8 * colg);
            float4 bb = *(const float4*)(b2 + colbase + 8 * colg + 4);
            bc[0] = ba.x; bc[1] = ba.y; bc[2] = ba.z; bc[3] = ba.w;
            bc[4] = bb.x; bc[5] = bb.y; bc[6] = bb.z; bc[7] = bb.w;
        }

        // two 64-col half passes: stage z -> entropy + top-k
        #pragma unroll
        for (int half = 0; half < 2; half++) {
            if (chalf == half) {
                #pragma unroll
                for (int i = 0; i < 8; i++) {
                    int r = 8 * rowg + i;
                    #pragma unroll
                    for (int j = 0; j < 4; j++) {
                        float2 v = unpack2(acc[i][j]);
                        int c = 8 * (colg & 7) + 2 * j;
                        z_s[r * ZP + c]     = v.x + bc[2 * j];
                        z_s[r * ZP + c + 1] = v.y + bc[2 * j + 1];
                    }
                }
            }
            __syncthreads();

            // epilogue: entropy + top-k on raw logits (sigmoid is monotone)
            const int gbase = colbase + half * 64;
            for (int i = 0; i < 32; i++) {
                int cc = esub + 2 * i;
                float z = z_s[erow * ZP + cc];
                // -s*ln(s) = ln(1+e^-z)/(1+e^-z); clamp for overflow safety
                float t = __expf(fminf(-z, 80.f));
                float a = 1.f + t;
                ent += __fdividef(__logf(a), a);
                if (z > mn) {
                    int gcol = gbase + cc;
                    #pragma unroll
                    for (int s = 0; s < KTOP; s++)
                        if (s == mnpos) { tv[s] = z; ti[s] = gcol; }
                    mn = tv[0]; mnpos = 0;
                    #pragma unroll
                    for (int s = 1; s < KTOP; s++)
                        if (tv[s] < mn) { mn = tv[s]; mnpos = s; }
                }
            }
            __syncthreads();
        }
        // next tile's w_s staging is safe: all w_s reads done before the
        // half-pass syncs above.
    }

    // write candidates (2 streams per row x NSPLIT stripes = 240/row)
    {
        int rowglob = row0 + erow;
        int base = ((rowglob * NSPLIT + by) * 2 + esub) * KTOP;
        #pragma unroll
        for (int s = 0; s < KTOP; s++) {
            g_candv[base + s] = tv[s];
            g_candi[base + s] = ti[s];
        }
    }

    // deterministic entropy reduction (tree in smem, no atomics)
    __syncthreads();
    z_s[tid] = ent;
    __syncthreads();
    #pragma unroll
    for (int off = 128; off > 0; off >>= 1) {
        if (tid < off) z_s[tid] += z_s[tid + off];
        __syncthreads();
    }
    if (tid == 0) g_entp[bx * NSPLIT + by] = z_s[0];
}

// =====================================================================
// Kernel 3: per-row merge of 240 candidates -> ordered top-15,
// gather tf, apply 4 ops weighted by op_w, write ratio_tensor.
// One warp per row. Lexicographic (value desc, index asc) = jax.top_k.
// =====================================================================
__global__ __launch_bounds__(128) void merge_kernel(float* __restrict__ out)
{
    const int warp = threadIdx.x >> 5;
    const int lane = threadIdx.x & 31;
    const int row = blockIdx.x * 4 + warp;

    float cv[8]; int ci[8];
    #pragma unroll
    for (int j = 0; j < 8; j++) {
        int s = lane + 32 * j;
        if (s < NCAND) {
            cv[j] = g_candv[row * NCAND + s];
            ci[j] = g_candi[row * NCAND + s];
        } else {
            cv[j] = -1e30f; ci[j] = 0x7fffffff;
        }
    }

    float ow0 = g_opw[row * 4 + 0], ow1 = g_opw[row * 4 + 1];
    float ow2 = g_opw[row * 4 + 2], ow3 = g_opw[row * 4 + 3];

    unsigned used = 0;
    for (int rank = 0; rank < KTOP; rank++) {
        float lv = -1e30f; int li = 0x7fffffff; int ls = -1;
        #pragma unroll
        for (int j = 0; j < 8; j++) {
            bool free = !((used >> j) & 1u);
            if (free && (cv[j] > lv || (cv[j] == lv && ci[j] < li))) {
                lv = cv[j]; li = ci[j]; ls = j;
            }
        }
        float gv = lv; int gi = li;
        #pragma unroll
        for (int off = 16; off > 0; off >>= 1) {
            float ov = __shfl_xor_sync(0xffffffffu, gv, off);
            int oi = __shfl_xor_sync(0xffffffffu, gi, off);
            if (ov > gv || (ov == gv && oi < gi)) { gv = ov; gi = oi; }
        }
        if (ls >= 0 && lv == gv && li == gi) used |= 1u << ls;

        if (lane == 0) {
            float sel = __fdividef(1.f, 1.f + __expf(-gv));
            int ii = gi >> 8, jj = gi & 255;
            float fi = g_tf[row * F + ii];
            float fj = g_tf[row * F + jj];
            float ratio = fi / (fabsf(fj) + 1e-8f);
            float lr = logf(fabsf(fi) + 1e-8f) - logf(fabsf(fj) + 1e-8f);
            float rt = ratio * ow0 + lr * ow1 + (fi - fj) * ow2 + (fi * fj) * ow3;
            out[row * KTOP + rank] = rt;
            g_topsel[row * KTOP + rank] = sel;
        }
    }
}

// =====================================================================
// Kernel 4: batch means. 35 independent reduction tasks, one block each
// (deterministic tree reductions, no atomics).
// task 0..14: pair_importances; 15..29: ratio_mags; 30..33: op_prefs;
// 34: entropy.
// =====================================================================
__global__ __launch_bounds__(256) void final_kernel(float* __restrict__ out)
{
    __shared__ float red[256];
    const int tid = threadIdx.x;
    const int task = blockIdx.x;
    const float invB = 1.0f / (float)BATCH;

    float p = 0.f;
    if (task < 15) {
        for (int r = tid; r < BATCH; r += 256) p += g_topsel[r * KTOP + task];
    } else if (task < 30) {
        int k = task - 15;
        for (int r = tid; r < BATCH; r += 256) p += fabsf(out[r * KTOP + k]);
    } else if (task < 34) {
        int j = task - 30;
        for (int r = tid; r < BATCH; r += 256) p += g_opw[r * 4 + j];
    } else {
        if (tid < NRB * NSPLIT) p = g_entp[tid];
    }
    red[tid] = p;
    __syncthreads();
    #pragma unroll
    for (int off = 128; off > 0; off >>= 1) {
        if (tid < off) red[tid] += red[tid + off];
        __syncthreads();
    }
    if (tid == 0) {
        float v = red[0] * invB;
        if (task < 15)      out[PI_OFF + task] = v;
        else if (task < 30) out[RM_OFF + task - 15] = v;
        else if (task < 34) out[OP_OFF + task - 30] = v;
        else                out[ENT_OFF] = v;
    }
}

// =====================================================================
extern "C" void kernel_launch(void* const* d_in, const int* in_sizes, int n_in,
                              void* d_out, int out_size)
{
    const float* x     = (const float*)d_in[0];
    const float* rs_w1 = (const float*)d_in[1];
    const float* rs_b1 = (const float*)d_in[2];
    const float* rs_w2 = (const float*)d_in[3];
    const float* rs_b2 = (const float*)d_in[4];
    const float* os_w1 = (const float*)d_in[5];
    const float* os_b1 = (const float*)d_in[6];
    const float* os_w2 = (const float*)d_in[7];
    const float* os_b2 = (const float*)d_in[8];
    const float* ft_w1 = (const float*)d_in[9];
    const float* ft_b1 = (const float*)d_in[10];
    const float* ft_w2 = (const float*)d_in[11];
    const float* ft_b2 = (const float*)d_in[12];
    float* out = (float*)d_out;

    prep_kernel<<<BATCH / 8, 256>>>(x, rs_w1, rs_b1, os_w1, os_b1,
                                    os_w2, os_b2, ft_w1, ft_b1, ft_w2, ft_b2);

    const int smem_bytes = (HID * HP + HID * TC + RB * ZP) * (int)sizeof(float); // 166400
    cudaFuncSetAttribute(big_kernel, cudaFuncAttributeMaxDynamicSharedMemorySize,
                         smem_bytes);
    big_kernel<<<dim3(NRB, NSPLIT), 256, smem_bytes>>>(rs_w2, rs_b2);

    merge_kernel<<<BATCH / 4, 128>>>(out);
    final_kernel<<<35, 256>>>(out);
}

// round 5
// speedup vs baseline: 1.0221x; 1.0017x over previous
#include <cuda_runtime.h>
#include <math.h>

#define F 256
#define HID 128
#define BATCH 2048
#define KTOP 15
#define NPAIR 65536
#define NSPLIT 8
#define RB 128                   // rows per block in big kernel
#define TC 128                   // column tile
#define STRIPE (NPAIR / NSPLIT)  // 8192
#define NTILES (STRIPE / TC)     // 64
#define HP 132                   // h_s row pad
#define ZP 65                    // z_s row pad
#define NRB (BATCH / RB)         // 16 row blocks
#define NCAND (NSPLIT * 2 * KTOP)  // 240 candidates per row

// output layout offsets
#define PI_OFF (BATCH * KTOP)        // 30720
#define OP_OFF (PI_OFF + KTOP)       // 30735
#define RM_OFF (OP_OFF + 4)          // 30739
#define ENT_OFF (RM_OFF + KTOP)      // 30754

// -------- device scratch (static, no runtime alloc) --------
__device__ float g_hT[HID * BATCH];              // rs hidden, transposed [k][row]
__device__ float g_tf[BATCH * F];                // feature transform output
__device__ float g_opw[BATCH * 4];               // softmax op weights
__device__ float g_candv[BATCH * NCAND];         // top-k candidate logits
__device__ int   g_candi[BATCH * NCAND];         // top-k candidate pair indices
__device__ float g_entp[NRB * NSPLIT];           // per-CTA entropy partials (128)
__device__ float g_topsel[BATCH * KTOP];         // sigmoid values of winners

// -------- packed f32x2 helpers (sm_103a FFMA2 path) --------
__device__ __forceinline__ void ffma2(unsigned long long& d,
                                      unsigned long long a,
                                      unsigned long long b) {
    asm("fma.rn.f32x2 %0, %1, %2, %0;" : "+l"(d) : "l"(a), "l"(b));
}
__device__ __forceinline__ unsigned long long pack2(float lo, float hi) {
    unsigned long long r;
    asm("mov.b64 %0, {%1, %2};" : "=l"(r) : "f"(lo), "f"(hi));
    return r;
}
__device__ __forceinline__ float2 unpack2(unsigned long long v) {
    float2 r;
    asm("mov.b64 {%0, %1}, %2;" : "=f"(r.x), "=f"(r.y) : "l"(v));
    return r;
}

// =====================================================================
// Kernel 1: the three small MLPs. 8 rows per CTA, 256 threads.
// =====================================================================
__device__ __forceinline__ void hidden_layer(
    const float xs[8][F], const float* __restrict__ w1,
    const float* __restrict__ b1, int hcol, int rg, float out4[4])
{
    float a0 = 0.f, a1 = 0.f, a2 = 0.f, a3 = 0.f;
    #pragma unroll 4
    for (int f = 0; f < F; f++) {
        float wv = w1[f * HID + hcol];
        a0 = fmaf(xs[rg * 4 + 0][f], wv, a0);
        a1 = fmaf(xs[rg * 4 + 1][f], wv, a1);
        a2 = fmaf(xs[rg * 4 + 2][f], wv, a2);
        a3 = fmaf(xs[rg * 4 + 3][f], wv, a3);
    }
    float bb = b1[hcol];
    out4[0] = fmaxf(a0 + bb, 0.f);
    out4[1] = fmaxf(a1 + bb, 0.f);
    out4[2] = fmaxf(a2 + bb, 0.f);
    out4[3] = fmaxf(a3 + bb, 0.f);
}

__global__ __launch_bounds__(256) void prep_kernel(
    const float* __restrict__ x,
    const float* __restrict__ rs_w1, const float* __restrict__ rs_b1,
    const float* __restrict__ os_w1, const float* __restrict__ os_b1,
    const float* __restrict__ os_w2, const float* __restrict__ os_b2,
    const float* __restrict__ ft_w1, const float* __restrict__ ft_b1,
    const float* __restrict__ ft_w2, const float* __restrict__ ft_b2)
{
    __shared__ float xs[8][F];
    __shared__ float hb[8][HID];
    __shared__ float lg[8][4];
    const int tid = threadIdx.x;
    const int row0 = blockIdx.x * 8;

    for (int idx = tid; idx < 8 * F; idx += 256) {
        int r = idx >> 8, c = idx & (F - 1);
        xs[r][c] = x[(row0 + r) * F + c];
    }
    __syncthreads();

    const int hcol = tid & (HID - 1);
    const int rg = tid >> 7;   // 0..1

    // ---- rs hidden -> g_hT (transposed layout for the big kernel) ----
    {
        float h4[4];
        hidden_layer(xs, rs_w1, rs_b1, hcol, rg, h4);
        #pragma unroll
        for (int j = 0; j < 4; j++)
            g_hT[hcol * BATCH + row0 + rg * 4 + j] = h4[j];
    }

    // ---- ft hidden -> hb ----
    {
        float h4[4];
        hidden_layer(xs, ft_w1, ft_b1, hcol, rg, h4);
        #pragma unroll
        for (int j = 0; j < 4; j++) hb[rg * 4 + j][hcol] = h4[j];
    }
    __syncthreads();

    // ---- tf = hb @ ft_w2 + ft_b2 ----
    {
        const int o = tid;   // 0..255
        float a[8];
        #pragma unroll
        for (int r = 0; r < 8; r++) a[r] = 0.f;
        #pragma unroll 4
        for (int k = 0; k < HID; k++) {
            float wv = ft_w2[k * F + o];
            #pragma unroll
            for (int r = 0; r < 8; r++) a[r] = fmaf(hb[r][k], wv, a[r]);
        }
        float bb = ft_b2[o];
        #pragma unroll
        for (int r = 0; r < 8; r++)
            g_tf[(row0 + r) * F + o] = a[r] + bb;
    }
    __syncthreads();

    // ---- os hidden -> hb ----
    {
        float h4[4];
        hidden_layer(xs, os_w1, os_b1, hcol, rg, h4);
        #pragma unroll
        for (int j = 0; j < 4; j++) hb[rg * 4 + j][hcol] = h4[j];
    }
    __syncthreads();

    // ---- op logits ----
    if (tid < 32) {
        int r = tid >> 2, j = tid & 3;
        float a = os_b2[j];
        #pragma unroll 4
        for (int k = 0; k < HID; k++) a = fmaf(hb[r][k], os_w2[k * 4 + j], a);
        lg[r][j] = a;
    }
    __syncthreads();
    // ---- softmax over 4 ops ----
    if (tid < 8) {
        float l0 = lg[tid][0], l1 = lg[tid][1], l2 = lg[tid][2], l3 = lg[tid][3];
        float m = fmaxf(fmaxf(l0, l1), fmaxf(l2, l3));
        float e0 = __expf(l0 - m), e1 = __expf(l1 - m);
        float e2 = __expf(l2 - m), e3 = __expf(l3 - m);
        float inv = __fdividef(1.f, e0 + e1 + e2 + e3);
        g_opw[(row0 + tid) * 4 + 0] = e0 * inv;
        g_opw[(row0 + tid) * 4 + 1] = e1 * inv;
        g_opw[(row0 + tid) * 4 + 2] = e2 * inv;
        g_opw[(row0 + tid) * 4 + 3] = e3 * inv;
    }
}

// =====================================================================
// Kernel 2: fused [128,128]x[128,8192] logit GEMM + entropy + top-k.
// grid (16 row-blocks, 8 stripes) = 128 CTAs, 256 threads, 1 CTA/SM.
// Per-thread GEMM micro-tile: 8 rows x 8 cols via packed fma.rn.f32x2
// (32 FFMA2/thread/k -> 128 lane-MACs/cyc/SM, 2x the FFMA floor).
// Epilogue in two 64-col passes through padded smem staging.
// =====================================================================
extern __shared__ float smem2[];

__global__ __launch_bounds__(256, 1) void big_kernel(
    const float* __restrict__ w2, const float* __restrict__ b2)
{
    float* h_s = smem2;                  // [HID][HP]     67,584 B
    float* w_s = h_s + HID * HP;         // [HID][TC]     65,536 B
    float* z_s = w_s + HID * TC;         // [RB][ZP]      33,280 B

    const int tid = threadIdx.x;
    const int bx = blockIdx.x;           // row block 0..15
    const int by = blockIdx.y;           // stripe 0..7
    const int row0 = bx * RB;

    // load h (already transposed in global): coalesced, conflict-free STS
    for (int idx = tid; idx < HID * RB; idx += 256) {
        int k = idx >> 7;
        int r = idx & (RB - 1);
        h_s[k * HP + r] = g_hT[k * BATCH + row0 + r];
    }

    // per-thread top-k state (register arrays, fully unrolled access)
    float tv[KTOP];
    int ti[KTOP];
    #pragma unroll
    for (int s = 0; s < KTOP; s++) { tv[s] = -1e30f; ti[s] = 0x7fffffff; }
    float mn = -1e30f;
    int mnpos = 0;
    float ent = 0.f;

    const int rowg = tid >> 4;   // 0..15: rows 8*rowg..+7
    const int colg = tid & 15;   // 0..15: cols 8*colg..+7
    const int chalf = colg >> 3; // which 64-col half this thread's cols are in
    const int erow = tid >> 1;   // epilogue row 0..127
    const int esub = tid & 1;

    __syncthreads();

    for (int tile = 0; tile < NTILES; tile++) {
        const int colbase = by * STRIPE + tile * TC;

        // stage w2 tile [128 x 128] into smem (coalesced LDG.128)
        #pragma unroll
        for (int i = 0; i < 16; i++) {
            int idx4 = tid + i * 256;              // 0..4095 float4s
            int k = idx4 >> 5;
            int c4 = (idx4 & 31) << 2;
            float4 v = *(const float4*)(w2 + (size_t)k * NPAIR + colbase + c4);
            *(float4*)(w_s + k * TC + c4) = v;
        }
        __syncthreads();

        unsigned long long acc[8][4];
        #pragma unroll
        for (int i = 0; i < 8; i++)
            #pragma unroll
            for (int j = 0; j < 4; j++) acc[i][j] = 0ull;

        #pragma unroll 4
        for (int k = 0; k < HID; k++) {
            const float4 hv0 = *(const float4*)(h_s + k * HP + 8 * rowg);
            const float4 hv1 = *(const float4*)(h_s + k * HP + 8 * rowg + 4);
            const ulonglong2 wv0 = *(const ulonglong2*)(w_s + k * TC + 8 * colg);
            const ulonglong2 wv1 = *(const ulonglong2*)(w_s + k * TC + 8 * colg + 4);
            const unsigned long long wp[4] = {wv0.x, wv0.y, wv1.x, wv1.y};
            const float hr[8] = {hv0.x, hv0.y, hv0.z, hv0.w,
                                 hv1.x, hv1.y, hv1.z, hv1.w};
            #pragma unroll
            for (int i = 0; i < 8; i++) {
                unsigned long long hs = pack2(hr[i], hr[i]);
                #pragma unroll
                for (int j = 0; j < 4; j++) ffma2(acc[i][j], hs, wp[j]);
            }
        }

        // bias (per-thread 8 cols)
        float bc[8];
        {
            float4 ba = *(const float4*)(b2 + colbase + 8 * colg);
            float4 bb = *(const float4*)(b2 + colbase + 8 * colg + 4);
            bc[0] = ba.x; bc[1] = ba.y; bc[2] = ba.z; bc[3] = ba.w;
            bc[4] = bb.x; bc[5] = bb.y; bc[6] = bb.z; bc[7] = bb.w;
        }

        // two 64-col half passes: stage z -> entropy + top-k
        #pragma unroll
        for (int half = 0; half < 2; half++) {
            if (chalf == half) {
                #pragma unroll
                for (int i = 0; i < 8; i++) {
                    int r = 8 * rowg + i;
                    #pragma unroll
                    for (int j = 0; j < 4; j++) {
                        float2 v = unpack2(acc[i][j]);
                        int c = 8 * (colg & 7) + 2 * j;
                        z_s[r * ZP + c]     = v.x + bc[2 * j];
                        z_s[r * ZP + c + 1] = v.y + bc[2 * j + 1];
                    }
                }
            }
            __syncthreads();

            // epilogue: entropy + top-k on raw logits (sigmoid is monotone)
            const int gbase = colbase + half * 64;
            for (int i = 0; i < 32; i++) {
                int cc = esub + 2 * i;
                float z = z_s[erow * ZP + cc];
                // -s*ln(s) = ln(1+e^-z)/(1+e^-z); clamp for overflow safety
                float t = __expf(fminf(-z, 80.f));
                float a = 1.f + t;
                ent += __fdividef(__logf(a), a);
                if (z > mn) {
                    int gcol = gbase + cc;
                    #pragma unroll
                    for (int s = 0; s < KTOP; s++)
                        if (s == mnpos) { tv[s] = z; ti[s] = gcol; }
                    mn = tv[0]; mnpos = 0;
                    #pragma unroll
                    for (int s = 1; s < KTOP; s++)
                        if (tv[s] < mn) { mn = tv[s]; mnpos = s; }
                }
            }
            __syncthreads();
        }
        // next tile's w_s staging is safe: all w_s reads done before the
        // half-pass syncs above.
    }

    // write candidates (2 streams per row x NSPLIT stripes = 240/row)
    {
        int rowglob = row0 + erow;
        int base = ((rowglob * NSPLIT + by) * 2 + esub) * KTOP;
        #pragma unroll
        for (int s = 0; s < KTOP; s++) {
            g_candv[base + s] = tv[s];
            g_candi[base + s] = ti[s];
        }
    }

    // deterministic entropy reduction (tree in smem, no atomics)
    __syncthreads();
    z_s[tid] = ent;
    __syncthreads();
    #pragma unroll
    for (int off = 128; off > 0; off >>= 1) {
        if (tid < off) z_s[tid] += z_s[tid + off];
        __syncthreads();
    }
    if (tid == 0) g_entp[bx * NSPLIT + by] = z_s[0];
}

// =====================================================================
// Kernel 3: per-row merge of 240 candidates -> ordered top-15,
// gather tf, apply 4 ops weighted by op_w, write ratio_tensor.
// One warp per row. Lexicographic (value desc, index asc) = jax.top_k.
// =====================================================================
__global__ __launch_bounds__(128) void merge_kernel(float* __restrict__ out)
{
    const int warp = threadIdx.x >> 5;
    const int lane = threadIdx.x & 31;
    const int row = blockIdx.x * 4 + warp;

    float cv[8]; int ci[8];
    #pragma unroll
    for (int j = 0; j < 8; j++) {
        int s = lane + 32 * j;
        if (s < NCAND) {
            cv[j] = g_candv[row * NCAND + s];
            ci[j] = g_candi[row * NCAND + s];
        } else {
            cv[j] = -1e30f; ci[j] = 0x7fffffff;
        }
    }

    float ow0 = g_opw[row * 4 + 0], ow1 = g_opw[row * 4 + 1];
    float ow2 = g_opw[row * 4 + 2], ow3 = g_opw[row * 4 + 3];

    unsigned used = 0;
    for (int rank = 0; rank < KTOP; rank++) {
        float lv = -1e30f; int li = 0x7fffffff; int ls = -1;
        #pragma unroll
        for (int j = 0; j < 8; j++) {
            bool free = !((used >> j) & 1u);
            if (free && (cv[j] > lv || (cv[j] == lv && ci[j] < li))) {
                lv = cv[j]; li = ci[j]; ls = j;
            }
        }
        float gv = lv; int gi = li;
        #pragma unroll
        for (int off = 16; off > 0; off >>= 1) {
            float ov = __shfl_xor_sync(0xffffffffu, gv, off);
            int oi = __shfl_xor_sync(0xffffffffu, gi, off);
            if (ov > gv || (ov == gv && oi < gi)) { gv = ov; gi = oi; }
        }
        if (ls >= 0 && lv == gv && li == gi) used |= 1u << ls;

        if (lane == 0) {
            float sel = __fdividef(1.f, 1.f + __expf(-gv));
            int ii = gi >> 8, jj = gi & 255;
            float fi = g_tf[row * F + ii];
            float fj = g_tf[row * F + jj];
            float ratio = fi / (fabsf(fj) + 1e-8f);
            float lr = logf(fabsf(fi) + 1e-8f) - logf(fabsf(fj) + 1e-8f);
            float rt = ratio * ow0 + lr * ow1 + (fi - fj) * ow2 + (fi * fj) * ow3;
            out[row * KTOP + rank] = rt;
            g_topsel[row * KTOP + rank] = sel;
        }
    }
}

// =====================================================================
// Kernel 4: batch means. 35 independent reduction tasks, one block each
// (deterministic tree reductions, no atomics).
// task 0..14: pair_importances; 15..29: ratio_mags; 30..33: op_prefs;
// 34: entropy.
// =====================================================================
__global__ __launch_bounds__(256) void final_kernel(float* __restrict__ out)
{
    __shared__ float red[256];
    const int tid = threadIdx.x;
    const int task = blockIdx.x;
    const float invB = 1.0f / (float)BATCH;

    float p = 0.f;
    if (task < 15) {
        for (int r = tid; r < BATCH; r += 256) p += g_topsel[r * KTOP + task];
    } else if (task < 30) {
        int k = task - 15;
        for (int r = tid; r < BATCH; r += 256) p += fabsf(out[r * KTOP + k]);
    } else if (task < 34) {
        int j = task - 30;
        for (int r = tid; r < BATCH; r += 256) p += g_opw[r * 4 + j];
    } else {
        if (tid < NRB * NSPLIT) p = g_entp[tid];
    }
    red[tid] = p;
    __syncthreads();
    #pragma unroll
    for (int off = 128; off > 0; off >>= 1) {
        if (tid < off) red[tid] += red[tid + off];
        __syncthreads();
    }
    if (tid == 0) {
        float v = red[0] * invB;
        if (task < 15)      out[PI_OFF + task] = v;
        else if (task < 30) out[RM_OFF + task - 15] = v;
        else if (task < 34) out[OP_OFF + task - 30] = v;
        else                out[ENT_OFF] = v;
    }
}

// =====================================================================
extern "C" void kernel_launch(void* const* d_in, const int* in_sizes, int n_in,
                              void* d_out, int out_size)
{
    const float* x     = (const float*)d_in[0];
    const float* rs_w1 = (const float*)d_in[1];
    const float* rs_b1 = (const float*)d_in[2];
    const float* rs_w2 = (const float*)d_in[3];
    const float* rs_b2 = (const float*)d_in[4];
    const float* os_w1 = (const float*)d_in[5];
    const float* os_b1 = (const float*)d_in[6];
    const float* os_w2 = (const float*)d_in[7];
    const float* os_b2 = (const float*)d_in[8];
    const float* ft_w1 = (const float*)d_in[9];
    const float* ft_b1 = (const float*)d_in[10];
    const float* ft_w2 = (const float*)d_in[11];
    const float* ft_b2 = (const float*)d_in[12];
    float* out = (float*)d_out;

    prep_kernel<<<BATCH / 8, 256>>>(x, rs_w1, rs_b1, os_w1, os_b1,
                                    os_w2, os_b2, ft_w1, ft_b1, ft_w2, ft_b2);

    const int smem_bytes = (HID * HP + HID * TC + RB * ZP) * (int)sizeof(float); // 166400
    cudaFuncSetAttribute(big_kernel, cudaFuncAttributeMaxDynamicSharedMemorySize,
                         smem_bytes);
    big_kernel<<<dim3(NRB, NSPLIT), 256, smem_bytes>>>(rs_w2, rs_b2);

    merge_kernel<<<BATCH / 4, 128>>>(out);
    final_kernel<<<35, 256>>>(out);
}

// round 14
// speedup vs baseline: 1.0408x; 1.0183x over previous
#include <cuda_runtime.h>
#include <cuda_bf16.h>
#include <math.h>
#include <stdint.h>

#define F 256
#define HID 128
#define BATCH 2048
#define KTOP 15
#define NPAIR 65536
#define NSPLIT 8
#define RB 128                   // rows per block in big kernel
#define TCN 128                  // column tile (pairs per tile)
#define STRIPE (NPAIR / NSPLIT)  // 8192
#define NTILES (STRIPE / TCN)    // 64 tiles per stripe
#define NTILE_TOT (NPAIR / TCN)  // 512 tiles total
#define NRB (BATCH / RB)         // 16 row blocks
#define NCAND (NSPLIT * 4 * KTOP)  // 480 candidates per row

// output layout offsets
#define PI_OFF (BATCH * KTOP)
#define OP_OFF (PI_OFF + KTOP)
#define RM_OFF (OP_OFF + 4)
#define ENT_OFF (RM_OFF + KTOP)

// big kernel smem layout (bytes from dynamic smem base)
// stage: 64 rows x 132 floats (128 cols + 4 pad)  = 33792 B
#define SP 132
#define RED_OFF 0
#define STG_OFF 1024
#define A_OFF   (STG_OFF + 64 * SP * 4)      // 34816
#define B_OFF   (A_OFF + 65536)              // 100352
#define SMEM_TOTAL (B_OFF + 2 * 65536)       // 231424

// -------- device scratch (static, no runtime alloc) --------
__device__ float g_h[BATCH * HID];               // rs hidden, row-major
__device__ uint4 g_B[NTILE_TOT * 4096];          // pre-swizzled bf16 w tiles (hi|lo)
__device__ uint4 g_A[NRB * 4096];                // pre-swizzled bf16 h tiles (hi|lo)
__device__ float g_tf[BATCH * F];                // feature transform output
__device__ float g_opw[BATCH * 4];               // softmax op weights
__device__ float g_candv[BATCH * NCAND];         // top-k candidate logits
__device__ int   g_candi[BATCH * NCAND];         // top-k candidate pair indices
__device__ float g_entp[NRB * NSPLIT];           // per-CTA entropy partials (128)
__device__ float g_topsel[BATCH * KTOP];         // sigmoid values of winners

// ================= helpers (base-PTX only: no tcgen05) =================
__device__ __forceinline__ uint32_t smem_u32(const void* p) {
    uint32_t a;
    asm("{ .reg .u64 t; cvta.to.shared.u64 t, %1; cvt.u32.u64 %0, t; }"
        : "=r"(a) : "l"(p));
    return a;
}
#define SMEM_SWZ(off) ((off) ^ (((off) >> 3) & 0x70))

__device__ __forceinline__ void cp16(uint32_t dst, const void* src) {
    asm volatile("cp.async.cg.shared.global [%0], [%1], 16;"
                 :: "r"(dst), "l"(src) : "memory");
}
#define CP_COMMIT() asm volatile("cp.async.commit_group;" ::: "memory")
#define CP_WAIT0()  asm volatile("cp.async.wait_group 0;" ::: "memory")

__device__ __forceinline__ void ldsm4(uint32_t* r, uint32_t addr) {
    asm volatile("ldmatrix.sync.aligned.m8n8.x4.shared.b16 {%0,%1,%2,%3}, [%4];"
                 : "=r"(r[0]), "=r"(r[1]), "=r"(r[2]), "=r"(r[3]) : "r"(addr));
}
__device__ __forceinline__ void mma_bf16(float* d, const uint32_t* a,
                                         uint32_t b0, uint32_t b1) {
    asm volatile(
        "mma.sync.aligned.m16n8k16.row.col.f32.bf16.bf16.f32 "
        "{%0,%1,%2,%3}, {%4,%5,%6,%7}, {%8,%9}, {%0,%1,%2,%3};"
        : "+f"(d[0]), "+f"(d[1]), "+f"(d[2]), "+f"(d[3])
        : "r"(a[0]), "r"(a[1]), "r"(a[2]), "r"(a[3]), "r"(b0), "r"(b1));
}

// =====================================================================
// Kernel 1: the three small MLPs. 8 rows per CTA, 256 threads.
// =====================================================================
__device__ __forceinline__ void hidden_layer(
    const float xs[8][F], const float* __restrict__ w1,
    const float* __restrict__ b1, int hcol, int rg, float out4[4])
{
    float a0 = 0.f, a1 = 0.f, a2 = 0.f, a3 = 0.f;
    #pragma unroll 4
    for (int f = 0; f < F; f++) {
        float wv = w1[f * HID + hcol];
        a0 = fmaf(xs[rg * 4 + 0][f], wv, a0);
        a1 = fmaf(xs[rg * 4 + 1][f], wv, a1);
        a2 = fmaf(xs[rg * 4 + 2][f], wv, a2);
        a3 = fmaf(xs[rg * 4 + 3][f], wv, a3);
    }
    float bb = b1[hcol];
    out4[0] = fmaxf(a0 + bb, 0.f);
    out4[1] = fmaxf(a1 + bb, 0.f);
    out4[2] = fmaxf(a2 + bb, 0.f);
    out4[3] = fmaxf(a3 + bb, 0.f);
}

__global__ __launch_bounds__(256) void prep_kernel(
    const float* __restrict__ x,
    const float* __restrict__ rs_w1, const float* __restrict__ rs_b1,
    const float* __restrict__ os_w1, const float* __restrict__ os_b1,
    const float* __restrict__ os_w2, const float* __restrict__ os_b2,
    const float* __restrict__ ft_w1, const float* __restrict__ ft_b1,
    const float* __restrict__ ft_w2, const float* __restrict__ ft_b2)
{
    __shared__ float xs[8][F];
    __shared__ float hb[8][HID];
    __shared__ float lg[8][4];
    const int tid = threadIdx.x;
    const int row0 = blockIdx.x * 8;

    for (int idx = tid; idx < 8 * F; idx += 256) {
        int r = idx >> 8, c = idx & (F - 1);
        xs[r][c] = x[(row0 + r) * F + c];
    }
    __syncthreads();

    const int hcol = tid & (HID - 1);
    const int rg = tid >> 7;

    // ---- rs hidden -> g_h (row-major) ----
    {
        float h4[4];
        hidden_layer(xs, rs_w1, rs_b1, hcol, rg, h4);
        #pragma unroll
        for (int j = 0; j < 4; j++)
            g_h[(row0 + rg * 4 + j) * HID + hcol] = h4[j];
    }

    // ---- ft hidden -> hb ----
    {
        float h4[4];
        hidden_layer(xs, ft_w1, ft_b1, hcol, rg, h4);
        #pragma unroll
        for (int j = 0; j < 4; j++) hb[rg * 4 + j][hcol] = h4[j];
    }
    __syncthreads();

    // ---- tf = hb @ ft_w2 + ft_b2 ----
    {
        const int o = tid;
        float a[8];
        #pragma unroll
        for (int r = 0; r < 8; r++) a[r] = 0.f;
        #pragma unroll 4
        for (int k = 0; k < HID; k++) {
            float wv = ft_w2[k * F + o];
            #pragma unroll
            for (int r = 0; r < 8; r++) a[r] = fmaf(hb[r][k], wv, a[r]);
        }
        float bb = ft_b2[o];
        #pragma unroll
        for (int r = 0; r < 8; r++)
            g_tf[(row0 + r) * F + o] = a[r] + bb;
    }
    __syncthreads();

    // ---- os hidden -> hb ----
    {
        float h4[4];
        hidden_layer(xs, os_w1, os_b1, hcol, rg, h4);
        #pragma unroll
        for (int j = 0; j < 4; j++) hb[rg * 4 + j][hcol] = h4[j];
    }
    __syncthreads();

    if (tid < 32) {
        int r = tid >> 2, j = tid & 3;
        float a = os_b2[j];
        #pragma unroll 4
        for (int k = 0; k < HID; k++) a = fmaf(hb[r][k], os_w2[k * 4 + j], a);
        lg[r][j] = a;
    }
    __syncthreads();
    if (tid < 8) {
        float l0 = lg[tid][0], l1 = lg[tid][1], l2 = lg[tid][2], l3 = lg[tid][3];
        float m = fmaxf(fmaxf(l0, l1), fmaxf(l2, l3));
        float e0 = __expf(l0 - m), e1 = __expf(l1 - m);
        float e2 = __expf(l2 - m), e3 = __expf(l3 - m);
        float inv = __fdividef(1.f, e0 + e1 + e2 + e3);
        g_opw[(row0 + tid) * 4 + 0] = e0 * inv;
        g_opw[(row0 + tid) * 4 + 1] = e1 * inv;
        g_opw[(row0 + tid) * 4 + 2] = e2 * inv;
        g_opw[(row0 + tid) * 4 + 3] = e3 * inv;
    }
}

// =====================================================================
// Kernel 1b: split w2 into bf16 hi/lo, pre-swizzled SW128 tile images.
// Tile t: pairs [128t,128t+128). Image row = pair p, 64 bf16 k per chunk.
// Tile byte layout: [hi c0 16K][hi c1 16K][lo c0 16K][lo c1 16K].
// =====================================================================
union BfPack { __nv_bfloat16 b[8]; uint4 u; };

__global__ __launch_bounds__(256) void conv_w_kernel(const float* __restrict__ w2)
{
    const int t = blockIdx.x >> 1;
    const int c = blockIdx.x & 1;
    char* dst = (char*)(g_B + (size_t)t * 4096);
    const int tid = threadIdx.x;

    for (int it = 0; it < 4; it++) {
        int idx = it * 256 + tid;          // 0..1023
        int p = idx & 127;
        int g = idx >> 7;                  // 0..7
        BfPack hi, lo;
        #pragma unroll
        for (int i = 0; i < 8; i++) {
            float v = w2[(size_t)(64 * c + 8 * g + i) * NPAIR + 128 * t + p];
            __nv_bfloat16 h = __float2bfloat16(v);
            hi.b[i] = h;
            lo.b[i] = __float2bfloat16(v - __bfloat162float(h));
        }
        uint32_t off = (uint32_t)(p * 128 + g * 16);
        uint32_t sw = SMEM_SWZ(off);
        *(uint4*)(dst + c * 16384 + sw) = hi.u;
        *(uint4*)(dst + 32768 + c * 16384 + sw) = lo.u;
    }
}

// Kernel 1c: same for h rows -> g_A (16 rowblock tiles). grid = 32 blocks.
__global__ __launch_bounds__(256) void conv_h_kernel()
{
    const int rb = blockIdx.x >> 1;
    const int c = blockIdx.x & 1;
    char* dst = (char*)(g_A + (size_t)rb * 4096);
    const int tid = threadIdx.x;

    for (int it = 0; it < 4; it++) {
        int idx = it * 256 + tid;
        int r = idx & 127;
        int g = idx >> 7;
        BfPack hi, lo;
        #pragma unroll
        for (int i = 0; i < 8; i++) {
            float v = g_h[(size_t)(rb * 128 + r) * HID + 64 * c + 8 * g + i];
            __nv_bfloat16 h = __float2bfloat16(v);
            hi.b[i] = h;
            lo.b[i] = __float2bfloat16(v - __bfloat162float(h));
        }
        uint32_t off = (uint32_t)(r * 128 + g * 16);
        uint32_t sw = SMEM_SWZ(off);
        *(uint4*)(dst + c * 16384 + sw) = hi.u;
        *(uint4*)(dst + 32768 + c * 16384 + sw) = lo.u;
    }
}

// =====================================================================
// Kernel 2: mma.sync bf16 3-term split GEMM + fused entropy + top-k.
// grid (16 row-blocks, 8 stripes) = 128 CTAs, 256 threads (8 warps).
// Warp (mg = wid&3, ch = wid>>2) owns out rows mg*32..+31, cols ch*64..+63.
// Per tile: 24 k16 steps (K'=384: hi*hi + hi*lo(B) + lo(A)*hi), 16 mma each.
// Epilogue: two 64-row x 128-col passes through [64][SP] smem stage;
// per-thread dual top-15 lists (one per pass row), column stream = col%4.
// B double-buffered via cp.async.
// =====================================================================
extern __shared__ char smem_raw[];

// topk update macro (register arrays, fully unrolled predicated writes)
#define TOPK_UPDATE(tvA, tiA, mnA, mpA, zval, gcol)                  \
    if ((zval) > (mnA)) {                                            \
        _Pragma("unroll")                                            \
        for (int s = 0; s < KTOP; s++)                               \
            if (s == (mpA)) { tvA[s] = (zval); tiA[s] = (gcol); }    \
        mnA = tvA[0]; mpA = 0;                                       \
        _Pragma("unroll")                                            \
        for (int s = 1; s < KTOP; s++)                               \
            if (tvA[s] < mnA) { mnA = tvA[s]; mpA = s; }             \
    }

__global__ __launch_bounds__(256, 1) void big_kernel(const float* __restrict__ b2)
{
    const int tid = threadIdx.x;
    const int wid = tid >> 5;
    const int lane = tid & 31;
    const int bx = blockIdx.x;           // row block 0..15
    const int by = blockIdx.y;           // stripe 0..7
    const uint32_t smem = smem_u32(smem_raw);

    const int mg = wid & 3;              // m-group
    const int ch = wid >> 2;             // col half
    const int g = lane >> 2, c = lane & 3;

    // ---- initial async loads: A image (64KB) + B tile 0 (64KB) ----
    {
        const uint4* srcA = g_A + (size_t)bx * 4096;
        uint32_t dA = smem + A_OFF + tid * 16;
        #pragma unroll
        for (int i = 0; i < 16; i++) cp16(dA + i * 4096, srcA + tid + 256 * i);
        const uint4* srcB = g_B + (size_t)(by * NTILES) * 4096;
        uint32_t dB = smem + B_OFF + tid * 16;
        #pragma unroll
        for (int i = 0; i < 16; i++) cp16(dB + i * 4096, srcB + tid + 256 * i);
        CP_COMMIT();
        CP_WAIT0();
    }
    __syncthreads();

    // ---- ldmatrix per-lane address precompute ----
    // image: row r (128B, SW128) -> addr = base + r*128 + (kb ^ ((r&7)<<4))
    const int quad = lane >> 3, lrow = lane & 7;
    const int qlo = quad & 1;
    const uint32_t kaddb = (uint32_t)((quad >> 1) * 16);  // +8 k half (bytes)
    const int rowA = mg * 32 + qlo * 8 + lrow;
    const int rowB = ch * 64 + qlo * 8 + lrow;
    const uint32_t axor = (uint32_t)((rowA & 7) << 4);
    const uint32_t bxor = (uint32_t)((rowB & 7) << 4);
    const uint32_t aAddr0 = smem + A_OFF + rowA * 128;
    const uint32_t bAddr0 = smem + B_OFF + rowB * 128;

    // dual per-thread top-k state (pass0 row, pass1 row)
    float tv0[KTOP], tv1[KTOP];
    int ti0[KTOP], ti1[KTOP];
    #pragma unroll
    for (int s = 0; s < KTOP; s++) {
        tv0[s] = -1e30f; ti0[s] = 0x7fffffff;
        tv1[s] = -1e30f; ti1[s] = 0x7fffffff;
    }
    float mn0 = -1e30f, mn1 = -1e30f;
    int mp0 = 0, mp1 = 0;
    float ent = 0.f;

    const int erow = tid >> 2;           // stage row 0..63
    const int q = tid & 3;               // col residue (stream id)
    float* stage = (float*)(smem_raw + STG_OFF);

    for (int t = 0; t < NTILES; t++) {
        const int cur = t & 1;

        // ---- prefetch next B tile (overlaps with mma) ----
        if (t + 1 < NTILES) {
            const uint4* srcB = g_B + (size_t)(by * NTILES + t + 1) * 4096;
            uint32_t dB = smem + B_OFF + (cur ^ 1) * 65536 + tid * 16;
            #pragma unroll
            for (int i = 0; i < 16; i++) cp16(dB + i * 4096, srcB + tid + 256 * i);
            CP_COMMIT();
        }

        const int colbase = (by * NTILES + t) * TCN;

        // ---- acc init = bias (per-thread cols shared by both m-blocks) ----
        float acc[2][8][4];
        #pragma unroll
        for (int nb = 0; nb < 8; nb++) {
            float2 bv = *(const float2*)(b2 + colbase + ch * 64 + nb * 8 + 2 * c);
            #pragma unroll
            for (int mb = 0; mb < 2; mb++) {
                acc[mb][nb][0] = bv.x; acc[mb][nb][1] = bv.y;
                acc[mb][nb][2] = bv.x; acc[mb][nb][3] = bv.y;
            }
        }

        // ---- 3-term split mainloop: seg0 hiA*hiB, seg1 hiA*loB, seg2 loA*hiB
        const uint32_t bBufB = bAddr0 + cur * 65536;
        #pragma unroll
        for (int seg = 0; seg < 3; seg++) {
            const uint32_t aSeg = aAddr0 + ((seg == 2) ? 32768u : 0u);
            const uint32_t bSeg = bBufB + ((seg == 1) ? 32768u : 0u);
            #pragma unroll
            for (int chk = 0; chk < 2; chk++) {
                #pragma unroll
                for (int ks = 0; ks < 4; ks++) {
                    const uint32_t kb = (uint32_t)(ks * 32) + kaddb;
                    const uint32_t aOff = aSeg + chk * 16384 + (kb ^ axor);
                    const uint32_t bOff = bSeg + chk * 16384 + (kb ^ bxor);
                    uint32_t a0[4], a1[4];
                    ldsm4(a0, aOff);           // rows mg*32..+15
                    ldsm4(a1, aOff + 2048);    // rows +16
                    #pragma unroll
                    for (int nb2 = 0; nb2 < 4; nb2++) {
                        uint32_t r[4];
                        ldsm4(r, bOff + nb2 * 2048);
                        mma_bf16(acc[0][2 * nb2],     a0, r[0], r[2]);
                        mma_bf16(acc[0][2 * nb2 + 1], a0, r[1], r[3]);
                        mma_bf16(acc[1][2 * nb2],     a1, r[0], r[2]);
                        mma_bf16(acc[1][2 * nb2 + 1], a1, r[1], r[3]);
                    }
                }
            }
        }

        // ---- epilogue: two 64-row x 128-col passes through smem stage ----
        #pragma unroll
        for (int p = 0; p < 2; p++) {
            {   // write this pass's m16 block (global rows mg*32 + p*16 + lr)
                const int rs_lo = mg * 16 + g;
                const int colb = ch * 64 + 2 * c;
                #pragma unroll
                for (int nb = 0; nb < 8; nb++) {
                    *(float2*)(stage + rs_lo * SP + colb + nb * 8) =
                        make_float2(acc[p][nb][0], acc[p][nb][1]);
                    *(float2*)(stage + (rs_lo + 8) * SP + colb + nb * 8) =
                        make_float2(acc[p][nb][2], acc[p][nb][3]);
                }
            }
            __syncthreads();
            {   // scan 32 cols (stride-4 stream q) of stage row erow
                const float* srow = stage + erow * SP + q;
                const int cb = colbase + q;
                #pragma unroll 4
                for (int i = 0; i < 32; i++) {
                    float z = srow[4 * i];
                    // -s*ln(s) = ln(1+e^-z)/(1+e^-z)
                    float tt = __expf(fminf(-z, 80.f));
                    float a = 1.f + tt;
                    ent += __fdividef(__logf(a), a);
                    int gcol = cb + 4 * i;
                    if (p == 0) {
                        TOPK_UPDATE(tv0, ti0, mn0, mp0, z, gcol)
                    } else {
                        TOPK_UPDATE(tv1, ti1, mn1, mp1, z, gcol)
                    }
                }
            }
            __syncthreads();
        }

        CP_WAIT0();
        __syncthreads();   // next B buffer ready; stage free
    }

    // ---- write candidates: 4 streams per row (col mod 4) x 8 stripes ----
    {
        const int r0 = (erow >> 4) * 32 + (erow & 15);   // pass0 row (local)
        const int r1 = r0 + 16;                          // pass1 row
        const int base0 = (((bx * RB + r0) * NSPLIT + by) * 4 + q) * KTOP;
        const int base1 = (((bx * RB + r1) * NSPLIT + by) * 4 + q) * KTOP;
        #pragma unroll
        for (int s = 0; s < KTOP; s++) {
            g_candv[base0 + s] = tv0[s];
            g_candi[base0 + s] = ti0[s];
            g_candv[base1 + s] = tv1[s];
            g_candi[base1 + s] = ti1[s];
        }
    }

    // ---- deterministic entropy reduction ----
    float* red = (float*)(smem_raw + RED_OFF);
    red[tid] = ent;
    __syncthreads();
    #pragma unroll
    for (int off = 128; off > 0; off >>= 1) {
        if (tid < off) red[tid] += red[tid + off];
        __syncthreads();
    }
    if (tid == 0) g_entp[bx * NSPLIT + by] = red[0];
}

// =====================================================================
// Kernel 3: per-row merge of 480 candidates -> ordered top-15.
// One warp per row; 15 candidates per lane. Lexicographic
// (value desc, index asc) matches jax.lax.top_k.
// =====================================================================
__global__ __launch_bounds__(128) void merge_kernel(float* __restrict__ out)
{
    const int warp = threadIdx.x >> 5;
    const int lane = threadIdx.x & 31;
    const int row = blockIdx.x * 4 + warp;

    float cv[15]; int ci[15];
    #pragma unroll
    for (int j = 0; j < 15; j++) {
        int s = lane + 32 * j;           // 0..479
        cv[j] = g_candv[row * NCAND + s];
        ci[j] = g_candi[row * NCAND + s];
    }

    float ow0 = g_opw[row * 4 + 0], ow1 = g_opw[row * 4 + 1];
    float ow2 = g_opw[row * 4 + 2], ow3 = g_opw[row * 4 + 3];

    unsigned used = 0;
    for (int rank = 0; rank < KTOP; rank++) {
        float lv = -1e30f; int li = 0x7fffffff; int ls = -1;
        #pragma unroll
        for (int j = 0; j < 15; j++) {
            bool free = !((used >> j) & 1u);
            if (free && (cv[j] > lv || (cv[j] == lv && ci[j] < li))) {
                lv = cv[j]; li = ci[j]; ls = j;
            }
        }
        float gv = lv; int gi = li;
        #pragma unroll
        for (int off = 16; off > 0; off >>= 1) {
            float ov = __shfl_xor_sync(0xffffffffu, gv, off);
            int oi = __shfl_xor_sync(0xffffffffu, gi, off);
            if (ov > gv || (ov == gv && oi < gi)) { gv = ov; gi = oi; }
        }
        if (ls >= 0 && lv == gv && li == gi) used |= 1u << ls;

        if (lane == 0) {
            float sel = __fdividef(1.f, 1.f + __expf(-gv));
            int ii = gi >> 8, jj = gi & 255;
            float fi = g_tf[row * F + ii];
            float fj = g_tf[row * F + jj];
            float ratio = fi / (fabsf(fj) + 1e-8f);
            float lr = logf(fabsf(fi) + 1e-8f) - logf(fabsf(fj) + 1e-8f);
            float rt = ratio * ow0 + lr * ow1 + (fi - fj) * ow2 + (fi * fj) * ow3;
            out[row * KTOP + rank] = rt;
            g_topsel[row * KTOP + rank] = sel;
        }
    }
}

// =====================================================================
// Kernel 4: batch means. 35 independent reduction tasks, one block each.
// =====================================================================
__global__ __launch_bounds__(256) void final_kernel(float* __restrict__ out)
{
    __shared__ float red[256];
    const int tid = threadIdx.x;
    const int task = blockIdx.x;
    const float invB = 1.0f / (float)BATCH;

    float p = 0.f;
    if (task < 15) {
        for (int r = tid; r < BATCH; r += 256) p += g_topsel[r * KTOP + task];
    } else if (task < 30) {
        int k = task - 15;
        for (int r = tid; r < BATCH; r += 256) p += fabsf(out[r * KTOP + k]);
    } else if (task < 34) {
        int j = task - 30;
        for (int r = tid; r < BATCH; r += 256) p += g_opw[r * 4 + j];
    } else {
        if (tid < NRB * NSPLIT) p = g_entp[tid];
    }
    red[tid] = p;
    __syncthreads();
    #pragma unroll
    for (int off = 128; off > 0; off >>= 1) {
        if (tid < off) red[tid] += red[tid + off];
        __syncthreads();
    }
    if (tid == 0) {
        float v = red[0] * invB;
        if (task < 15)      out[PI_OFF + task] = v;
        else if (task < 30) out[RM_OFF + task - 15] = v;
        else if (task < 34) out[OP_OFF + task - 30] = v;
        else                out[ENT_OFF] = v;
    }
}

// =====================================================================
extern "C" void kernel_launch(void* const* d_in, const int* in_sizes, int n_in,
                              void* d_out, int out_size)
{
    const float* x     = (const float*)d_in[0];
    const float* rs_w1 = (const float*)d_in[1];
    const float* rs_b1 = (const float*)d_in[2];
    const float* rs_w2 = (const float*)d_in[3];
    const float* rs_b2 = (const float*)d_in[4];
    const float* os_w1 = (const float*)d_in[5];
    const float* os_b1 = (const float*)d_in[6];
    const float* os_w2 = (const float*)d_in[7];
    const float* os_b2 = (const float*)d_in[8];
    const float* ft_w1 = (const float*)d_in[9];
    const float* ft_b1 = (const float*)d_in[10];
    const float* ft_w2 = (const float*)d_in[11];
    const float* ft_b2 = (const float*)d_in[12];
    float* out = (float*)d_out;

    prep_kernel<<<BATCH / 8, 256>>>(x, rs_w1, rs_b1, os_w1, os_b1,
                                    os_w2, os_b2, ft_w1, ft_b1, ft_w2, ft_b2);
    conv_w_kernel<<<NTILE_TOT * 2, 256>>>(rs_w2);
    conv_h_kernel<<<NRB * 2, 256>>>();

    cudaFuncSetAttribute(big_kernel, cudaFuncAttributeMaxDynamicSharedMemorySize,
                         SMEM_TOTAL);
    big_kernel<<<dim3(NRB, NSPLIT), 256, SMEM_TOTAL>>>(rs_b2);

    merge_kernel<<<BATCH / 4, 128>>>(out);
    final_kernel<<<35, 256>>>(out);
}